// round 17
// baseline (speedup 1.0000x reference)
#include <cuda_runtime.h>
#include <math.h>

// Problem constants
#define T_STEPS 1024
#define D_IN    2048
#define NH      2048
#define CATS    1000

// Recurrence kernel config
#define NBLK    128          // persistent blocks (1 block/SM)
#define NTH     512          // 16 warps
#define HPB     16           // hidden indices owned per block (z AND ht)
#define NSTAGE  26           // rows of U pinned in SMEM per block (of 32)
#define PREP    4            // p-ring replicas (hot-line fan-out)
#define GREP    8            // gen-flag replicas
// smem: U rows + two p buffers (p_t, p_{t+1}) + 128 partials
#define SMEM_FLOATS (NSTAGE*NH + 2*NH + 128)
#define SMEM_BYTES  (SMEM_FLOATS * 4)   // 229888 B

// Scratch (device globals; no allocation allowed)
__device__ float g_XZ[T_STEPS * NH];
__device__ float g_XH[T_STEPS * NH];
__device__ float g_Pb[PREP][4][NH];   // replicated p ring (slot = gen & 3)
__device__ float g_LOGITS[1024];
// Barrier: one count line + GREP gen lines (64 uints = 256B apart)
__device__ unsigned int g_count[64];
__device__ unsigned int g_gen[GREP * 64];

// ---------------------------------------------------------------------------
// GEMM v2 (round-12 proven): 128x128 tile, BK=8, 256 thr, 8x8 microtile,
// double-buffered smem, one __syncthreads per K-chunk, 2 blocks/SM.
// ---------------------------------------------------------------------------
#define TBM 128
#define TBN 128
#define TBK 8

__global__ __launch_bounds__(256, 2) void gemm_xproj(
    const float* __restrict__ x,
    const float* __restrict__ Wz,
    const float* __restrict__ Wh)
{
    __shared__ float As[2][TBK][132];
    __shared__ float Bs[2][TBK][132];

    const int tid  = threadIdx.x;
    const int row0 = blockIdx.y * TBM;
    const int col0 = blockIdx.x * TBN;

    const float* Bbase = (col0 < NH) ? (Wz + (size_t)col0 * D_IN)
                                     : (Wh + (size_t)(col0 - NH) * D_IN);

    const int tx = tid & 15;
    const int ty = tid >> 4;
    const int lr = tid >> 1;
    const int lk = (tid & 1) * 4;

    const float* aptr = x + (size_t)(row0 + lr) * D_IN + lk;
    const float* bptr = Bbase + (size_t)lr * D_IN + lk;

    float acc[8][8];
    #pragma unroll
    for (int i = 0; i < 8; i++)
        #pragma unroll
        for (int j = 0; j < 8; j++) acc[i][j] = 0.f;

    float4 av = *(const float4*)aptr;
    float4 bv = *(const float4*)bptr;
    As[0][lk + 0][lr] = av.x; As[0][lk + 1][lr] = av.y;
    As[0][lk + 2][lr] = av.z; As[0][lk + 3][lr] = av.w;
    Bs[0][lk + 0][lr] = bv.x; Bs[0][lk + 1][lr] = bv.y;
    Bs[0][lk + 2][lr] = bv.z; Bs[0][lk + 3][lr] = bv.w;
    __syncthreads();

    int cur = 0;
    for (int kt = 0; kt < D_IN; kt += TBK) {
        const bool more = (kt + TBK < D_IN);
        if (more) {
            av = *(const float4*)(aptr + kt + TBK);
            bv = *(const float4*)(bptr + kt + TBK);
        }
        #pragma unroll
        for (int k = 0; k < TBK; k++) {
            float a[8], b[8];
            *(float4*)&a[0] = *(const float4*)&As[cur][k][tx * 4];
            *(float4*)&a[4] = *(const float4*)&As[cur][k][64 + tx * 4];
            *(float4*)&b[0] = *(const float4*)&Bs[cur][k][ty * 4];
            *(float4*)&b[4] = *(const float4*)&Bs[cur][k][64 + ty * 4];
            #pragma unroll
            for (int i = 0; i < 8; i++)
                #pragma unroll
                for (int j = 0; j < 8; j++) acc[i][j] += a[i] * b[j];
        }
        if (more) {
            const int nb = cur ^ 1;
            As[nb][lk + 0][lr] = av.x; As[nb][lk + 1][lr] = av.y;
            As[nb][lk + 2][lr] = av.z; As[nb][lk + 3][lr] = av.w;
            Bs[nb][lk + 0][lr] = bv.x; Bs[nb][lk + 1][lr] = bv.y;
            Bs[nb][lk + 2][lr] = bv.z; Bs[nb][lk + 3][lr] = bv.w;
            __syncthreads();
            cur = nb;
        }
    }

    #pragma unroll
    for (int i = 0; i < 8; i++) {
        const int t = row0 + ((i < 4) ? (tx * 4 + i) : (64 + tx * 4 + i - 4));
        #pragma unroll
        for (int jh = 0; jh < 2; jh++) {
            const int n = col0 + ((jh == 0) ? (ty * 4) : (64 + ty * 4));
            float4 v = make_float4(acc[i][jh * 4 + 0], acc[i][jh * 4 + 1],
                                   acc[i][jh * 4 + 2], acc[i][jh * 4 + 3]);
            if (n < NH) *(float4*)&g_XZ[(size_t)t * NH + n] = v;
            else        *(float4*)&g_XH[(size_t)t * NH + (n - NH)] = v;
        }
    }
}

// ---------------------------------------------------------------------------
// Barrier arrive+wait. One arrival counter; gen replicated GREP ways so each
// block polls its own line (releaser fans out 8 release stores).
// ---------------------------------------------------------------------------
__device__ __forceinline__ void barrier_arrive_wait(unsigned int target, int b)
{
    unsigned int old;
    asm volatile("atom.acq_rel.gpu.global.add.u32 %0, [%1], 1;"
                 : "=r"(old) : "l"(&g_count[0]));
    if (old == NBLK - 1) {
        asm volatile("st.relaxed.gpu.global.u32 [%0], %1;"
                     :: "l"(&g_count[0]), "r"(0u));
        #pragma unroll
        for (int r = 0; r < GREP; r++)
            asm volatile("st.release.gpu.global.u32 [%0], %1;"
                         :: "l"(&g_gen[r * 64]), "r"(target));
    } else {
        unsigned int v;
        unsigned int* myg = &g_gen[(b & (GREP - 1)) * 64];
        do {
            asm volatile("ld.acquire.gpu.global.u32 %0, [%1];"
                         : "=r"(v) : "l"(myg));
        } while ((int)(v - target) < 0);
    }
}

// ---------------------------------------------------------------------------
// Persistent recurrence, replicated p-ring exchange. Block b owns indices
// [16b,16b+16). Superstep m (t=2m): stage p_t, p_{t+1} from ring replica
// b&3; one fused U pass gives own-row gates for gens t+1, t+2; local
// 16-element rolls produce p_{t+2}, p_{t+3}[own], published to ALL replicas.
// ---------------------------------------------------------------------------
__global__ __launch_bounds__(NTH, 1) void gru_recurrence(
    const float* __restrict__ Uz, const float* __restrict__ Uh,
    const float* __restrict__ bz,
    const float* __restrict__ Wout,
    const float* __restrict__ zt0, const float* __restrict__ htilde0,
    const float* __restrict__ hprev0,
    float* __restrict__ out)
{
    extern __shared__ float sm[];
    float* smU  = sm;                    // NSTAGE * NH
    float* psA  = sm + NSTAGE * NH;      // NH : p_t stage
    float* psB  = psA + NH;              // NH : p_{t+1} stage
    float* part = psB + NH;              // 128 partials [w*8 + (vec*4+it)]

    const int tid  = threadIdx.x;
    const int w    = tid >> 5;
    const int lane = tid & 31;
    const int wp   = w & 7;              // row group
    const int kh   = w >> 3;             // K half
    const int b    = blockIdx.x;
    const int I0   = b * HPB;
    const int rep  = b & (PREP - 1);     // which p replica this block reads

    unsigned int base = 0;
    if (tid == 0)
        asm volatile("ld.relaxed.gpu.global.u32 %0, [%1];"
                     : "=r"(base) : "l"(&g_gen[(b & (GREP - 1)) * 64]));

    // Pin NSTAGE matvec rows into SMEM. Row s: s<16 -> Uz[I0+s], else Uh[I0+s-16].
    for (int s = 0; s < NSTAGE; s++) {
        const float* src = (s < 16) ? (Uz + (size_t)(I0 + s) * NH)
                                    : (Uh + (size_t)(I0 + s - 16) * NH);
        for (int i = tid; i < NH / 4; i += NTH)
            ((float4*)(smU + (size_t)s * NH))[i] = ((const float4*)src)[i];
    }

    float4* psA4 = (float4*)psA;
    float4* psB4 = (float4*)psB;

    // Gate-lane constants (warps 0-7, lanes 0-7): r = vec*4+it
    const bool gate_lane = (w < 8) && (lane < 8);
    const int g_vec = lane >> 2;         // 0: gen from p_t, 1: from p_{t+1}
    const int g_it  = lane & 3;          // row s = wp + 8*it
    const int g_i   = I0 + wp + 8 * (g_it & 1);   // hidden index of this gate
    const bool g_isz = (g_it < 2);
    const float bzv = gate_lane && g_isz ? __ldg(bz + g_i) : 0.f;

    // Per-warp row pointers (K-half slices; float4 index j*32+lane, j<8)
    const int s3 = wp + 24;                       // only it=3 can be residual
    const bool resid = (s3 >= NSTAGE);
    const float4* r0 = (const float4*)(smU + (size_t)(wp)      * NH + kh * 1024);
    const float4* r1 = (const float4*)(smU + (size_t)(wp + 8)  * NH + kh * 1024);
    const float4* r2 = (const float4*)(smU + (size_t)(wp + 16) * NH + kh * 1024);
    const float4* r3 = resid
        ? (const float4*)(Uh + (size_t)(I0 + s3 - 16) * NH + kh * 1024)
        : (const float4*)(smU + (size_t)s3 * NH + kh * 1024);

    // Prologue: publish p_0, p_1 for own indices to ALL replicas; barrier.
    if (tid < 16) {
        int i = I0 + tid;
        float p0 = hprev0[i];
        float z  = zt0[i], h = htilde0[i];
        float p1 = (1.f - z) * p0 + z * h;
        #pragma unroll
        for (int r = 0; r < PREP; r++) {
            g_Pb[r][0][i] = p0;
            g_Pb[r][1][i] = p1;
        }
    }
    __syncthreads();
    if (tid == 0) barrier_arrive_wait(base + 1, b);
    __syncthreads();

    // ---- supersteps: 2 timesteps, 1 fused U pass, 1 grid barrier ----
    for (int m = 0; m < T_STEPS / 2; m++) {
        const int t = 2 * m;

        // Stage p_t, p_{t+1} from own replica FIRST (longest latency).
        psA4[tid] = __ldcg((const float4*)g_Pb[rep][t & 3] + tid);
        psB4[tid] = __ldcg((const float4*)g_Pb[rep][(t + 1) & 3] + tid);

        // Gate-lane x projection for this superstep
        float xvv = 0.f;
        if (gate_lane) {
            xvv = g_isz ? __ldg(&g_XZ[(size_t)(t + g_vec) * NH + g_i])
                        : __ldg(&g_XH[(size_t)(t + g_vec) * NH + g_i]);
        }
        // Residual U row prefetch (L1-resident after first superstep)
        float4 upre[8];
        if (resid) {
            #pragma unroll
            for (int j = 0; j < 8; j++) upre[j] = __ldg(r3 + j * 32 + lane);
        }
        __syncthreads();

        // Fused dual matvec: one pass over U, FMA vs p_t AND p_{t+1}
        float aA0 = 0.f, aA1 = 0.f, aA2 = 0.f, aA3 = 0.f;
        float aB0 = 0.f, aB1 = 0.f, aB2 = 0.f, aB3 = 0.f;
        #pragma unroll
        for (int j = 0; j < 8; j++) {
            float4 pA = psA4[kh * 256 + j * 32 + lane];
            float4 pB = psB4[kh * 256 + j * 32 + lane];
            float4 u;
            u = r0[j * 32 + lane];
            aA0 += u.x * pA.x + u.y * pA.y + u.z * pA.z + u.w * pA.w;
            aB0 += u.x * pB.x + u.y * pB.y + u.z * pB.z + u.w * pB.w;
            u = r1[j * 32 + lane];
            aA1 += u.x * pA.x + u.y * pA.y + u.z * pA.z + u.w * pA.w;
            aB1 += u.x * pB.x + u.y * pB.y + u.z * pB.z + u.w * pB.w;
            u = r2[j * 32 + lane];
            aA2 += u.x * pA.x + u.y * pA.y + u.z * pA.z + u.w * pA.w;
            aB2 += u.x * pB.x + u.y * pB.y + u.z * pB.z + u.w * pB.w;
            u = resid ? upre[j] : r3[j * 32 + lane];
            aA3 += u.x * pA.x + u.y * pA.y + u.z * pA.z + u.w * pA.w;
            aB3 += u.x * pB.x + u.y * pB.y + u.z * pB.z + u.w * pB.w;
        }
        #pragma unroll
        for (int off = 16; off; off >>= 1) {
            aA0 += __shfl_xor_sync(0xffffffffu, aA0, off);
            aA1 += __shfl_xor_sync(0xffffffffu, aA1, off);
            aA2 += __shfl_xor_sync(0xffffffffu, aA2, off);
            aA3 += __shfl_xor_sync(0xffffffffu, aA3, off);
            aB0 += __shfl_xor_sync(0xffffffffu, aB0, off);
            aB1 += __shfl_xor_sync(0xffffffffu, aB1, off);
            aB2 += __shfl_xor_sync(0xffffffffu, aB2, off);
            aB3 += __shfl_xor_sync(0xffffffffu, aB3, off);
        }
        if (lane == 0) {
            float* pt = part + w * 8;
            pt[0] = aA0; pt[1] = aA1; pt[2] = aA2; pt[3] = aA3;
            pt[4] = aB0; pt[5] = aB1; pt[6] = aB2; pt[7] = aB3;
        }
        __syncthreads();

        // Warps 0-7: combine K-halves, gates (1/lane), local rolls, publish
        // own p_{t+2}, p_{t+3} to ALL replicas; named-barrier + early arrive.
        if (w < 8) {
            if (lane < 8) {
                float v = part[w * 8 + lane] + part[(w + 8) * 8 + lane];
                float g;
                if (g_isz) g = 1.f / (1.f + expf(-(xvv + v + bzv)));
                else       g = tanhf(xvv + v);
                const int L = lane & 1;
                float z1 = __shfl_sync(0xFFu, g, L);
                float h1 = __shfl_sync(0xFFu, g, 2 + L);
                float z2 = __shfl_sync(0xFFu, g, 4 + L);
                float h2 = __shfl_sync(0xFFu, g, 6 + L);
                if (lane < 2) {
                    const int i = I0 + wp + 8 * L;
                    float p1 = psB[i];
                    float p2 = (1.f - z1) * p1 + z1 * h1;
                    float p3 = (1.f - z2) * p2 + z2 * h2;
                    const int sl2 = (t + 2) & 3, sl3 = (t + 3) & 3;
                    #pragma unroll
                    for (int r = 0; r < PREP; r++) {
                        g_Pb[r][sl2][i] = p2;
                        g_Pb[r][sl3][i] = p3;
                    }
                }
            }
            asm volatile("bar.sync 1, 256;" ::: "memory");
            if (tid == 0) barrier_arrive_wait(base + m + 2, b);
        }
        __syncthreads();   // all warps held until chip-wide release
    }

    // p_1024 is in ring slot 0 (1024 & 3). Stage for logits.
    psA4[tid] = __ldcg((const float4*)g_Pb[rep][0] + tid);
    __syncthreads();

    // Logits: warp gw = b*16 + w covers 1000 rows
    {
        int gw = b * 16 + w;
        if (gw < CATS) {
            const float4* u4 = (const float4*)(Wout + (size_t)gw * NH);
            float acc = 0.f;
            #pragma unroll
            for (int j = 0; j < 16; j++) {
                float4 u = __ldg(u4 + j * 32 + lane);
                float4 p = psA4[j * 32 + lane];
                acc += u.x * p.x + u.y * p.y + u.z * p.z + u.w * p.w;
            }
            #pragma unroll
            for (int off = 16; off; off >>= 1)
                acc += __shfl_xor_sync(0xffffffffu, acc, off);
            if (lane == 0) g_LOGITS[gw] = acc;
        }
    }
    __syncthreads();
    if (tid == 0) barrier_arrive_wait(base + T_STEPS / 2 + 2, b);
    __syncthreads();

    // Softmax in block 0 (reduction buffer reuses psB)
    if (b == 0) {
        float* red = psB;
        float lm = -1e30f;
        for (int c = tid; c < CATS; c += NTH) lm = fmaxf(lm, __ldcg(&g_LOGITS[c]));
        __syncthreads();
        red[tid] = lm; __syncthreads();
        for (int o = NTH / 2; o; o >>= 1) {
            if (tid < o) red[tid] = fmaxf(red[tid], red[tid + o]);
            __syncthreads();
        }
        float mx = red[0]; __syncthreads();
        float ls = 0.f;
        for (int c = tid; c < CATS; c += NTH) ls += expf(__ldcg(&g_LOGITS[c]) - mx);
        red[tid] = ls; __syncthreads();
        for (int o = NTH / 2; o; o >>= 1) {
            if (tid < o) red[tid] += red[tid + o];
            __syncthreads();
        }
        float inv = 1.f / red[0];
        for (int c = tid; c < CATS; c += NTH)
            out[c] = expf(__ldcg(&g_LOGITS[c]) - mx) * inv;
    }
}

// ---------------------------------------------------------------------------
extern "C" void kernel_launch(void* const* d_in, const int* in_sizes, int n_in,
                              void* d_out, int out_size)
{
    const float* x       = (const float*)d_in[0];
    const float* Wh      = (const float*)d_in[1];
    const float* Wz      = (const float*)d_in[2];
    // d_in[3] = Wr, d_in[7] = Ur, d_in[8] = br: dead code in reference
    const float* Uh      = (const float*)d_in[4];
    const float* Uz      = (const float*)d_in[5];
    const float* bz      = (const float*)d_in[6];
    const float* Wout    = (const float*)d_in[9];
    // d_in[10] = h0: never read by the reference recurrence
    const float* zt0     = (const float*)d_in[11];
    const float* htilde0 = (const float*)d_in[12];
    const float* hprev0  = (const float*)d_in[13];
    float* out = (float*)d_out;

    dim3 ggrid((NH * 2) / TBN, T_STEPS / TBM);   // (32, 8)
    gemm_xproj<<<ggrid, 256>>>(x, Wz, Wh);

    cudaFuncSetAttribute(gru_recurrence,
                         cudaFuncAttributeMaxDynamicSharedMemorySize, SMEM_BYTES);
    gru_recurrence<<<NBLK, NTH, SMEM_BYTES>>>(Uz, Uh, bz, Wout,
                                              zt0, htilde0, hprev0, out);
}